// round 1
// baseline (speedup 1.0000x reference)
#include <cuda_runtime.h>
#include <cstdint>
#include <cstddef>

// Problem constants
#define BB   2
#define LL   512
#define HIN  1024
#define ENT  16
#define DD   50
#define TOT  850              // (ENT+1)*DD
#define NROWS (BB*LL)         // 1024, GEMM M
#define NMASK 511             // L-1
#define SCALE 0.14142135623730951f  // 1/sqrt(50)

// Scratch (device globals; no allocation allowed)
__device__ float g_proj_s[BB * (ENT + 1) * LL * DD];  // [b][e][l][d]
__device__ float g_proj_e[BB * (ENT + 1) * LL * DD];
__device__ float g_cd[BB * NMASK];

// ---------------------------------------------------------------------------
// Kernel 1: projection GEMM  X(1024x1024) @ W(1024x850) + bias, for both
// W_start (z=0) and W_end (z=1). Epilogue writes transposed [b][e][l][d].
// ---------------------------------------------------------------------------
#define GBM 128
#define GBN 128
#define GBK 8
#define GTM 8
#define GTN 8

__global__ __launch_bounds__(256) void sgemm_proj(
    const float* __restrict__ X,
    const float* __restrict__ W0, const float* __restrict__ bias0,
    const float* __restrict__ W1, const float* __restrict__ bias1)
{
    const float* W    = blockIdx.z ? W1 : W0;
    const float* bias = blockIdx.z ? bias1 : bias0;
    float* dst        = blockIdx.z ? g_proj_e : g_proj_s;

    const int N = TOT, K = HIN;
    const int m0 = blockIdx.y * GBM;
    const int n0 = blockIdx.x * GBN;

    __shared__ float As[GBK][GBM];
    __shared__ float Bs[GBK][GBN];

    const int tid = threadIdx.x;
    const int tx = tid & 15;     // 0..15 -> N direction
    const int ty = tid >> 4;     // 0..15 -> M direction

    // A-tile load mapping (float4 along K)
    const int a_m = tid >> 1;          // 0..127
    const int a_k = (tid & 1) * 4;     // 0 or 4
    // B-tile load mapping (scalar; N=850 rows are not 16B aligned)
    const int b_k = tid >> 5;          // 0..7
    const int b_n = (tid & 31) * 4;    // 0..124

    float acc[GTM][GTN];
    #pragma unroll
    for (int i = 0; i < GTM; i++)
        #pragma unroll
        for (int j = 0; j < GTN; j++) acc[i][j] = 0.f;

    for (int k0 = 0; k0 < K; k0 += GBK) {
        float4 av = *reinterpret_cast<const float4*>(
            X + (size_t)(m0 + a_m) * K + k0 + a_k);
        As[a_k + 0][a_m] = av.x;
        As[a_k + 1][a_m] = av.y;
        As[a_k + 2][a_m] = av.z;
        As[a_k + 3][a_m] = av.w;

        #pragma unroll
        for (int u = 0; u < 4; u++) {
            int col = n0 + b_n + u;
            Bs[b_k][b_n + u] = (col < N) ? W[(size_t)(k0 + b_k) * N + col] : 0.f;
        }
        __syncthreads();

        #pragma unroll
        for (int kk = 0; kk < GBK; kk++) {
            float a_frag[GTM], b_frag[GTN];
            #pragma unroll
            for (int i = 0; i < GTM; i++) a_frag[i] = As[kk][ty * GTM + i];
            #pragma unroll
            for (int j = 0; j < GTN; j++) b_frag[j] = Bs[kk][tx * GTN + j];
            #pragma unroll
            for (int i = 0; i < GTM; i++)
                #pragma unroll
                for (int j = 0; j < GTN; j++)
                    acc[i][j] = fmaf(a_frag[i], b_frag[j], acc[i][j]);
        }
        __syncthreads();
    }

    // Epilogue: add bias, scatter to [b][e][l][d]
    #pragma unroll
    for (int i = 0; i < GTM; i++) {
        int row = m0 + ty * GTM + i;         // 0..1023
        int bb  = row >> 9;                  // /512
        int l   = row & 511;
        #pragma unroll
        for (int j = 0; j < GTN; j++) {
            int col = n0 + tx * GTN + j;
            if (col < N) {
                int e = col / DD;
                int d = col - e * DD;
                dst[(((size_t)bb * (ENT + 1) + e) * LL + l) * DD + d] =
                    acc[i][j] + bias[col];
            }
        }
    }
}

// ---------------------------------------------------------------------------
// Kernel 2: RoPE in place on q/k (e < 16 only). fp64 angle for accuracy.
// ---------------------------------------------------------------------------
__global__ void rope_kernel()
{
    int idx = blockIdx.x * blockDim.x + threadIdx.x;
    const int total = 2 * BB * ENT * LL * (DD / 2);  // 819200
    if (idx >= total) return;

    int t = idx % (DD / 2); int r = idx / (DD / 2);
    int l = r % LL;          r /= LL;
    int e = r % ENT;         r /= ENT;
    int b = r % BB;          r /= BB;
    float* p = r ? g_proj_e : g_proj_s;

    double inv = exp(-((2.0 * t) / (double)DD) * log(10000.0));
    double ang = (double)l * inv;
    float c = (float)cos(ang);
    float s = (float)sin(ang);

    size_t base = (((size_t)b * (ENT + 1) + e) * LL + l) * DD + 2 * t;
    float x0 = p[base], x1 = p[base + 1];
    p[base]     = x0 * c - x1 * s;
    p[base + 1] = x1 * c + x0 * s;
}

// ---------------------------------------------------------------------------
// Kernel 3: conj_diag[b,i] = scale * dot(conj_start[b,i,:], conj_end[b,i+1,:])
// ---------------------------------------------------------------------------
__global__ void conj_kernel()
{
    int t = blockIdx.x * blockDim.x + threadIdx.x;
    if (t >= BB * NMASK) return;
    int b = t / NMASK, i = t % NMASK;
    const float* a = g_proj_s + (((size_t)b * (ENT + 1) + ENT) * LL + i) * DD;
    const float* c = g_proj_e + (((size_t)b * (ENT + 1) + ENT) * LL + (i + 1)) * DD;
    float s = 0.f;
    #pragma unroll
    for (int d = 0; d < DD; d++) s = fmaf(a[d], c[d], s);
    g_cd[t] = s * SCALE;
}

// ---------------------------------------------------------------------------
// Kernel 4 (fused, HBM-bound): per (i,j) thread
//   acc_b = sum_k cd[b,k] * mask[k,i,j]             (536 MB stream, the roofline)
//   out[b,i,j,e] = scale * dot(q[b,e,i,:], k[b,e,j,:]) + acc_b
// 16x16 (i,j) tile per 256-thread block; both batches share each mask load.
// ---------------------------------------------------------------------------
__global__ __launch_bounds__(256) void fused_kernel(
    const float* __restrict__ mask, float* __restrict__ out)
{
    __shared__ float scd[BB * NMASK];     // 1022
    __shared__ float sq[16 * DD];         // 800
    __shared__ float sk[16 * DD];

    const int tid = threadIdx.x;
    const int tx = tid & 15;   // j offset
    const int ty = tid >> 4;   // i offset

    for (int k = tid; k < BB * NMASK; k += 256) scd[k] = g_cd[k];

    const int i0 = blockIdx.y * 16, j0 = blockIdx.x * 16;
    const int i = i0 + ty, j = j0 + tx;
    const float* mp = mask + (size_t)i * LL + j;

    __syncthreads();

    // ---- mask reduction: 511 strided loads, unrolled x8 for MLP ----
    float a0 = 0.f, a1 = 0.f;
    int k = 0;
    for (; k + 8 <= NMASK; k += 8) {
        float m[8];
        #pragma unroll
        for (int u = 0; u < 8; u++) m[u] = mp[(size_t)(k + u) * (LL * LL)];
        #pragma unroll
        for (int u = 0; u < 8; u++) {
            a0 = fmaf(scd[k + u],          m[u], a0);
            a1 = fmaf(scd[NMASK + k + u],  m[u], a1);
        }
    }
    for (; k < NMASK; k++) {
        float m = mp[(size_t)k * (LL * LL)];
        a0 = fmaf(scd[k],         m, a0);
        a1 = fmaf(scd[NMASK + k], m, a1);
    }

    // ---- scores + epilogue ----
    for (int b = 0; b < BB; b++) {
        float sreg[ENT];
        const float amask = b ? a1 : a0;
        for (int e = 0; e < ENT; e++) {
            __syncthreads();
            const float* qb = g_proj_s + (((size_t)b * (ENT + 1) + e) * LL + i0) * DD;
            const float* kb = g_proj_e + (((size_t)b * (ENT + 1) + e) * LL + j0) * DD;
            for (int x = tid; x < 16 * DD; x += 256) {
                sq[x] = qb[x];   // tile rows are contiguous (stride DD)
                sk[x] = kb[x];
            }
            __syncthreads();
            float dot = 0.f;
            #pragma unroll
            for (int d = 0; d < DD; d++)
                dot = fmaf(sq[ty * DD + d], sk[tx * DD + d], dot);
            sreg[e] = dot * SCALE + amask;
        }
        // 16 contiguous e-values -> 4x float4 coalesced store
        float4* op = reinterpret_cast<float4*>(
            out + ((((size_t)b * LL + i) * LL + j) * ENT));
        #pragma unroll
        for (int v = 0; v < 4; v++)
            op[v] = make_float4(sreg[4 * v], sreg[4 * v + 1],
                                sreg[4 * v + 2], sreg[4 * v + 3]);
    }
}

// ---------------------------------------------------------------------------
extern "C" void kernel_launch(void* const* d_in, const int* in_sizes, int n_in,
                              void* d_out, int out_size)
{
    const float* X    = (const float*)d_in[0];  // input_hidden (2,512,1024)
    const float* mask = (const float*)d_in[1];  // mask_matrix (511,512,512)
    const float* Ws   = (const float*)d_in[2];  // W_start (1024,850)
    const float* bs   = (const float*)d_in[3];  // b_start (850,)
    const float* We   = (const float*)d_in[4];  // W_end (1024,850)
    const float* be   = (const float*)d_in[5];  // b_end (850,)
    float* out        = (float*)d_out;          // (2,512,512,16)

    dim3 ggrid((TOT + GBN - 1) / GBN, NROWS / GBM, 2);   // (7, 8, 2)
    sgemm_proj<<<ggrid, 256>>>(X, Ws, bs, We, be);

    const int rope_total = 2 * BB * ENT * LL * (DD / 2);
    rope_kernel<<<(rope_total + 255) / 256, 256>>>();

    conj_kernel<<<(BB * NMASK + 255) / 256, 256>>>();

    fused_kernel<<<dim3(LL / 16, LL / 16), 256>>>(mask, out);
}

// round 2
// speedup vs baseline: 1.3815x; 1.3815x over previous
#include <cuda_runtime.h>
#include <cstdint>
#include <cstddef>

#define BB   2
#define LL   512
#define HIN  1024
#define ENT  16
#define DD   50
#define TOT  850
#define PADN 896
#define NMASK 511
#define SCALE 0.14142135623730951f

// Scratch
__device__ float g_Wp[2 * HIN * PADN];
__device__ float g_proj_s[BB * (ENT + 1) * LL * DD];
__device__ float g_proj_e[BB * (ENT + 1) * LL * DD];
__device__ float g_cd[BB * NMASK];
__device__ float g_tcos[LL * (DD / 2)];
__device__ float g_tsin[LL * (DD / 2)];

// ---------------------------------------------------------------------------
// Kernel 0: pad W into [1024][896] (zero-filled tail) for aligned float4 loads
// ---------------------------------------------------------------------------
__global__ void pad_w(const float* __restrict__ W0, const float* __restrict__ W1)
{
    int idx = blockIdx.x * blockDim.x + threadIdx.x;
    const int total = 2 * HIN * PADN;
    if (idx >= total) return;
    int z = idx / (HIN * PADN);
    int r = idx - z * (HIN * PADN);
    int k = r / PADN, n = r - (r / PADN) * PADN;
    const float* W = z ? W1 : W0;
    g_Wp[idx] = (n < TOT) ? W[(size_t)k * TOT + n] : 0.f;
}

// ---------------------------------------------------------------------------
// Kernel 0b: RoPE cos/sin table in fp64, once (512 x 25)
// ---------------------------------------------------------------------------
__global__ void trig_table()
{
    int idx = blockIdx.x * blockDim.x + threadIdx.x;
    if (idx >= LL * (DD / 2)) return;
    int l = idx / (DD / 2), t = idx - l * (DD / 2);
    double inv = exp(-((2.0 * t) / (double)DD) * log(10000.0));
    double ang = (double)l * inv;
    g_tcos[idx] = (float)cos(ang);
    g_tsin[idx] = (float)sin(ang);
}

// ---------------------------------------------------------------------------
// Kernel 1: SGEMM 64x64x16, 128 threads, double-buffered, 448 blocks
// X(1024x1024) @ Wp(1024x896) + bias -> [b][e][l][d]
// ---------------------------------------------------------------------------
__global__ __launch_bounds__(128) void sgemm_proj(
    const float* __restrict__ X,
    const float* __restrict__ bias0, const float* __restrict__ bias1)
{
    const int z = blockIdx.z;
    const float* Wp  = g_Wp + (size_t)z * HIN * PADN;
    const float* bias = z ? bias1 : bias0;
    float* dst       = z ? g_proj_e : g_proj_s;

    __shared__ float As[2][16][68];
    __shared__ float Bs[2][16][68];

    const int tid = threadIdx.x;
    const int m0 = blockIdx.y * 64;
    const int n0 = blockIdx.x * 64;

    const int am = tid >> 1, ak = (tid & 1) * 8;
    const int bk = tid >> 3, bn = (tid & 7) * 4;

    const float* Aptr = X  + (size_t)(m0 + am) * HIN + ak;
    const float* Bptr = Wp + (size_t)bk * PADN + n0 + bn;

    float4 ra0, ra1, rb0, rb1;
    ra0 = *reinterpret_cast<const float4*>(Aptr);
    ra1 = *reinterpret_cast<const float4*>(Aptr + 4);
    rb0 = *reinterpret_cast<const float4*>(Bptr);
    rb1 = *reinterpret_cast<const float4*>(Bptr + 32);

    As[0][ak + 0][am] = ra0.x; As[0][ak + 1][am] = ra0.y;
    As[0][ak + 2][am] = ra0.z; As[0][ak + 3][am] = ra0.w;
    As[0][ak + 4][am] = ra1.x; As[0][ak + 5][am] = ra1.y;
    As[0][ak + 6][am] = ra1.z; As[0][ak + 7][am] = ra1.w;
    *reinterpret_cast<float4*>(&Bs[0][bk][bn])      = rb0;
    *reinterpret_cast<float4*>(&Bs[0][bk][bn + 32]) = rb1;
    __syncthreads();

    float acc[4][8];
    #pragma unroll
    for (int i = 0; i < 4; i++)
        #pragma unroll
        for (int j = 0; j < 8; j++) acc[i][j] = 0.f;

    const int ty = tid >> 3, tx = tid & 7;

    for (int t = 0; t < 64; t++) {
        const int cur = t & 1;
        if (t < 63) {
            ra0 = *reinterpret_cast<const float4*>(Aptr + (t + 1) * 16);
            ra1 = *reinterpret_cast<const float4*>(Aptr + (t + 1) * 16 + 4);
            rb0 = *reinterpret_cast<const float4*>(Bptr + (size_t)(t + 1) * 16 * PADN);
            rb1 = *reinterpret_cast<const float4*>(Bptr + (size_t)(t + 1) * 16 * PADN + 32);
        }
        #pragma unroll
        for (int kk = 0; kk < 16; kk++) {
            float4 av  = *reinterpret_cast<const float4*>(&As[cur][kk][ty * 4]);
            float4 bva = *reinterpret_cast<const float4*>(&Bs[cur][kk][tx * 8]);
            float4 bvb = *reinterpret_cast<const float4*>(&Bs[cur][kk][tx * 8 + 4]);
            const float a4[4] = {av.x, av.y, av.z, av.w};
            const float b8[8] = {bva.x, bva.y, bva.z, bva.w, bvb.x, bvb.y, bvb.z, bvb.w};
            #pragma unroll
            for (int i = 0; i < 4; i++)
                #pragma unroll
                for (int j = 0; j < 8; j++)
                    acc[i][j] = fmaf(a4[i], b8[j], acc[i][j]);
        }
        if (t < 63) {
            const int nxt = cur ^ 1;
            As[nxt][ak + 0][am] = ra0.x; As[nxt][ak + 1][am] = ra0.y;
            As[nxt][ak + 2][am] = ra0.z; As[nxt][ak + 3][am] = ra0.w;
            As[nxt][ak + 4][am] = ra1.x; As[nxt][ak + 5][am] = ra1.y;
            As[nxt][ak + 6][am] = ra1.z; As[nxt][ak + 7][am] = ra1.w;
            *reinterpret_cast<float4*>(&Bs[nxt][bk][bn])      = rb0;
            *reinterpret_cast<float4*>(&Bs[nxt][bk][bn + 32]) = rb1;
            __syncthreads();
        }
    }

    #pragma unroll
    for (int i = 0; i < 4; i++) {
        int row = m0 + ty * 4 + i;
        int bb = row >> 9, l = row & 511;
        #pragma unroll
        for (int j = 0; j < 8; j++) {
            int col = n0 + tx * 8 + j;
            if (col < TOT) {
                int e = col / DD;
                int d = col - e * DD;
                dst[(((size_t)bb * (ENT + 1) + e) * LL + l) * DD + d] =
                    acc[i][j] + bias[col];
            }
        }
    }
}

// ---------------------------------------------------------------------------
// Kernel 2: RoPE apply (table lookup, float2, e<16 only) — memory bound
// ---------------------------------------------------------------------------
__global__ void rope_apply()
{
    int idx = blockIdx.x * blockDim.x + threadIdx.x;
    const int total = 2 * BB * ENT * LL * (DD / 2);
    if (idx >= total) return;

    int t = idx % (DD / 2); int r = idx / (DD / 2);
    int l = r % LL;          r /= LL;
    int e = r % ENT;         r /= ENT;
    int b = r % BB;          r /= BB;
    float* p = r ? g_proj_e : g_proj_s;

    float c = g_tcos[l * (DD / 2) + t];
    float s = g_tsin[l * (DD / 2) + t];

    size_t base = (((size_t)b * (ENT + 1) + e) * LL + l) * DD + 2 * t;
    float2 v = *reinterpret_cast<float2*>(&p[base]);
    float2 o;
    o.x = v.x * c - v.y * s;
    o.y = v.y * c + v.x * s;
    *reinterpret_cast<float2*>(&p[base]) = o;
}

// ---------------------------------------------------------------------------
// Kernel 3: conj_diag
// ---------------------------------------------------------------------------
__global__ void conj_kernel()
{
    int t = blockIdx.x * blockDim.x + threadIdx.x;
    if (t >= BB * NMASK) return;
    int b = t / NMASK, i = t - (t / NMASK) * NMASK;
    const float* a = g_proj_s + (((size_t)b * (ENT + 1) + ENT) * LL + i) * DD;
    const float* c = g_proj_e + (((size_t)b * (ENT + 1) + ENT) * LL + (i + 1)) * DD;
    float s = 0.f;
    #pragma unroll
    for (int d = 0; d < DD; d++) s = fmaf(a[d], c[d], s);
    g_cd[t] = s * SCALE;
}

// ---------------------------------------------------------------------------
// Kernel 4: fused mask-reduction + scores. Tile: 16 i x 64 j, 256 threads.
// Thread = (i=ty, j-quad=tx*4). Mask loads are float4 (coalesced 2x256B/warp).
// Even blocks: mask then scores; odd blocks: scores(b0), mask, rest — phase
// desync so DRAM streaming overlaps FMA across co-resident blocks.
// ---------------------------------------------------------------------------
struct FusedSmem {
    float skT[DD * 64];     // [d][j] transposed, 16B-aligned first
    float sqT[DD * 16];     // [d][i]
    float scd[BB * NMASK];
};

__device__ __forceinline__ void mask_phase(
    const float* __restrict__ mp, const float* __restrict__ scd,
    float4& a0, float4& a1)
{
    int k = 0;
    for (; k + 8 <= NMASK; k += 8) {
        float4 m[8];
        #pragma unroll
        for (int u = 0; u < 8; u++)
            m[u] = *reinterpret_cast<const float4*>(mp + (size_t)(k + u) * (LL * LL));
        #pragma unroll
        for (int u = 0; u < 8; u++) {
            float c0 = scd[k + u], c1 = scd[NMASK + k + u];
            a0.x = fmaf(c0, m[u].x, a0.x); a0.y = fmaf(c0, m[u].y, a0.y);
            a0.z = fmaf(c0, m[u].z, a0.z); a0.w = fmaf(c0, m[u].w, a0.w);
            a1.x = fmaf(c1, m[u].x, a1.x); a1.y = fmaf(c1, m[u].y, a1.y);
            a1.z = fmaf(c1, m[u].z, a1.z); a1.w = fmaf(c1, m[u].w, a1.w);
        }
    }
    for (; k < NMASK; k++) {
        float4 m = *reinterpret_cast<const float4*>(mp + (size_t)k * (LL * LL));
        float c0 = scd[k], c1 = scd[NMASK + k];
        a0.x = fmaf(c0, m.x, a0.x); a0.y = fmaf(c0, m.y, a0.y);
        a0.z = fmaf(c0, m.z, a0.z); a0.w = fmaf(c0, m.w, a0.w);
        a1.x = fmaf(c1, m.x, a1.x); a1.y = fmaf(c1, m.y, a1.y);
        a1.z = fmaf(c1, m.z, a1.z); a1.w = fmaf(c1, m.w, a1.w);
    }
}

__device__ __forceinline__ void score_pass(
    FusedSmem* sm, int b, int i0, int j0, int tid, int tx, int ty,
    float sreg[ENT][4])
{
    #pragma unroll 1
    for (int e = 0; e < ENT; e++) {
        __syncthreads();
        const float* qb = g_proj_s + (((size_t)b * (ENT + 1) + e) * LL + i0) * DD;
        const float* kb = g_proj_e + (((size_t)b * (ENT + 1) + e) * LL + j0) * DD;
        for (int x = tid; x < 16 * DD; x += 256) {
            int ii = x / DD, d = x - ii * DD;
            sm->sqT[d * 16 + ii] = qb[x];
        }
        for (int x = tid; x < 64 * DD; x += 256) {
            int jj = x / DD, d = x - jj * DD;
            sm->skT[d * 64 + jj] = kb[x];
        }
        __syncthreads();
        float r0 = 0.f, r1 = 0.f, r2 = 0.f, r3 = 0.f;
        #pragma unroll
        for (int d = 0; d < DD; d++) {
            float q = sm->sqT[d * 16 + ty];
            float4 kv = *reinterpret_cast<const float4*>(&sm->skT[d * 64 + tx * 4]);
            r0 = fmaf(q, kv.x, r0);
            r1 = fmaf(q, kv.y, r1);
            r2 = fmaf(q, kv.z, r2);
            r3 = fmaf(q, kv.w, r3);
        }
        sreg[e][0] = r0 * SCALE; sreg[e][1] = r1 * SCALE;
        sreg[e][2] = r2 * SCALE; sreg[e][3] = r3 * SCALE;
    }
}

__device__ __forceinline__ void store_b(
    float* __restrict__ out, int b, int i, int j0, int tx,
    const float sreg[ENT][4], const float4& am)
{
    const float a[4] = {am.x, am.y, am.z, am.w};
    #pragma unroll
    for (int jj = 0; jj < 4; jj++) {
        float4* op = reinterpret_cast<float4*>(
            out + ((((size_t)b * LL + i) * LL + (j0 + tx * 4 + jj)) * ENT));
        #pragma unroll
        for (int v = 0; v < 4; v++)
            op[v] = make_float4(sreg[4 * v + 0][jj] + a[jj],
                                sreg[4 * v + 1][jj] + a[jj],
                                sreg[4 * v + 2][jj] + a[jj],
                                sreg[4 * v + 3][jj] + a[jj]);
    }
}

__global__ __launch_bounds__(256) void fused_kernel(
    const float* __restrict__ mask, float* __restrict__ out)
{
    __shared__ FusedSmem sm;
    const int tid = threadIdx.x;
    const int tx = tid & 15, ty = tid >> 4;
    const int i0 = blockIdx.y * 16, j0 = blockIdx.x * 64;
    const int i = i0 + ty;

    for (int k = tid; k < BB * NMASK; k += 256) sm.scd[k] = g_cd[k];
    __syncthreads();

    const float* mp = mask + (size_t)i * LL + j0 + tx * 4;
    float4 a0 = make_float4(0.f, 0.f, 0.f, 0.f);
    float4 a1 = make_float4(0.f, 0.f, 0.f, 0.f);
    float sreg[ENT][4];

    if ((blockIdx.x + blockIdx.y) & 1) {
        // scores(b0) first, then mask stream, then store + scores(b1)
        score_pass(&sm, 0, i0, j0, tid, tx, ty, sreg);
        mask_phase(mp, sm.scd, a0, a1);
        store_b(out, 0, i, j0, tx, sreg, a0);
        score_pass(&sm, 1, i0, j0, tid, tx, ty, sreg);
        store_b(out, 1, i, j0, tx, sreg, a1);
    } else {
        mask_phase(mp, sm.scd, a0, a1);
        score_pass(&sm, 0, i0, j0, tid, tx, ty, sreg);
        store_b(out, 0, i, j0, tx, sreg, a0);
        score_pass(&sm, 1, i0, j0, tid, tx, ty, sreg);
        store_b(out, 1, i, j0, tx, sreg, a1);
    }
}

// ---------------------------------------------------------------------------
extern "C" void kernel_launch(void* const* d_in, const int* in_sizes, int n_in,
                              void* d_out, int out_size)
{
    const float* X    = (const float*)d_in[0];
    const float* mask = (const float*)d_in[1];
    const float* Ws   = (const float*)d_in[2];
    const float* bs   = (const float*)d_in[3];
    const float* We   = (const float*)d_in[4];
    const float* be   = (const float*)d_in[5];
    float* out        = (float*)d_out;

    {
        const int total = 2 * HIN * PADN;
        pad_w<<<(total + 255) / 256, 256>>>(Ws, We);
    }
    trig_table<<<(LL * (DD / 2) + 255) / 256, 256>>>();

    sgemm_proj<<<dim3(PADN / 64, 1024 / 64, 2), 128>>>(X, bs, be);

    {
        const int total = 2 * BB * ENT * LL * (DD / 2);
        rope_apply<<<(total + 255) / 256, 256>>>();
    }
    conj_kernel<<<(BB * NMASK + 255) / 256, 256>>>();

    fused_kernel<<<dim3(LL / 64, LL / 16), 256>>>(mask, out);
}